// round 6
// baseline (speedup 1.0000x reference)
#include <cuda_runtime.h>
#include <cuda_bf16.h>
#include <mma.h>
#include <math.h>
#include <stdint.h>

using namespace nvcuda;

#define B_BATCH 64
#define T_SEQ   2048
#define D_IN    1024
#define H1_DIM  512
#define H2_DIM  32
#define M_TOTAL (B_BATCH * T_SEQ)   // 131072

#define BK    64
#define A_LD  80    // bf16/row: 160B stride == 32 mod 128 -> conflict-free LDSM
#define B_LD  528   // bf16/row: 1056B stride == 32 mod 128 -> conflict-free LDSM

// ---- smem byte offsets ----
#define OFF_B0   0                    // 64 x 528 x 2 = 67584
#define OFF_B1   67584
#define OFF_A0   135168               // 64 x 80 x 2 = 10240
#define OFF_A1   145408               // mainloop ends 155648
#define OFF_HF   0                    // epilogue alias: fp32 [64][516] = 132096
#define OFF_HB   132096               // bf16 [64][520] = 66560
#define OFF_OUTS 198656               // fp32 [64][36] = 9216
#define OFF_B1S  207872               // fp32[512]
#define OFF_B2S  209920               // fp32[32]
#define OFF_W3S  210048               // fp32[32]
#define SMEM_TOTAL 210176

#define NTHREADS 512

// ---- device scratch ----
__device__ __nv_bfloat16 g_W1bf[D_IN * H1_DIM];   // [k][n] 1 MB
__device__ __nv_bfloat16 g_W2bf[H1_DIM * H2_DIM]; // 32 KB
__device__ float         g_logits[M_TOTAL];       // 512 KB

__device__ __forceinline__ uint32_t pack_bf16x2(float lo, float hi) {
    __nv_bfloat162 v = __floats2bfloat162_rn(lo, hi);
    return (uint32_t)__bfloat16_as_ushort(v.x) | ((uint32_t)__bfloat16_as_ushort(v.y) << 16);
}
__device__ __forceinline__ uint32_t smem_u32(const void* p) {
    uint32_t a;
    asm("{ .reg .u64 t; cvta.to.shared.u64 t, %1; cvt.u32.u64 %0, t; }" : "=r"(a) : "l"(p));
    return a;
}

// ============================================================
// Prep: convert W1, W2 to bf16
// ============================================================
__global__ void prep_kernel(const float* __restrict__ W1, const float* __restrict__ W2) {
    int i = blockIdx.x * blockDim.x + threadIdx.x;
    if (i < D_IN * H1_DIM)   g_W1bf[i] = __float2bfloat16(W1[i]);
    if (i < H1_DIM * H2_DIM) g_W2bf[i] = __float2bfloat16(W2[i]);
}

// ============================================================
// Fused kernel loaders (512 threads)
// ============================================================
__device__ __forceinline__ void ldgA(const float* __restrict__ Ap, int tid, float4 v[2]) {
#pragma unroll
    for (int it = 0; it < 2; it++) {
        int f = tid + it * NTHREADS;   // 0..1023
        int r = f >> 4;                // row 0..63
        int q = f & 15;                // float4 idx (64 floats/row)
        v[it] = *reinterpret_cast<const float4*>(Ap + (long)r * D_IN + q * 4);
    }
}
__device__ __forceinline__ void stsA(char* smem, uint32_t aoff, int tid, const float4 v[2]) {
#pragma unroll
    for (int it = 0; it < 2; it++) {
        int f = tid + it * NTHREADS;
        int r = f >> 4;
        int q = f & 15;
        uint2 u;
        u.x = pack_bf16x2(v[it].x, v[it].y);
        u.y = pack_bf16x2(v[it].z, v[it].w);
        *reinterpret_cast<uint2*>(smem + aoff + r * (A_LD * 2) + q * 8) = u;
    }
}
__device__ __forceinline__ void cpB(uint32_t b_base, const __nv_bfloat16* __restrict__ Bsrc, int tid) {
#pragma unroll
    for (int it = 0; it < 8; it++) {
        int c = tid + it * NTHREADS;   // 0..4095
        int row = c >> 6;              // k-row 0..63
        int ch  = c & 63;              // 16B chunk
        uint32_t off = (uint32_t)(row * (B_LD * 2) + ch * 16);
        uint64_t g = __cvta_generic_to_global((const void*)(Bsrc + (long)row * H1_DIM + ch * 8));
        asm volatile("cp.async.cg.shared.global [%0], [%1], 16;" :: "r"(b_base + off), "l"(g));
    }
}

__global__ __launch_bounds__(NTHREADS, 1)
void fused_kernel(const float* __restrict__ A,
                  const float* __restrict__ b1, const float* __restrict__ b2,
                  const float* __restrict__ W3, const float* __restrict__ b3) {
    extern __shared__ char smem[];
    const uint32_t sb = smem_u32(smem);
    const int tid = threadIdx.x;
    const int wid = tid >> 5;
    const long m0 = (long)blockIdx.x * 64;

    float* b1s = (float*)(smem + OFF_B1S);
    float* b2s = (float*)(smem + OFF_B2S);
    float* W3s = (float*)(smem + OFF_W3S);
    b1s[tid] = b1[tid];                         // all 512 threads
    if (tid < 32)                b2s[tid] = b2[tid];
    else if (tid < 64)           W3s[tid - 32] = W3[tid - 32];

    // warp layout: 2 (M) x 8 (N); warp tile 32 x 64
    const int wm = wid >> 3;   // 0..1
    const int wn = wid & 7;    // 0..7

    wmma::fragment<wmma::accumulator, 16, 16, 16, float> acc[2][4];
#pragma unroll
    for (int m = 0; m < 2; m++)
#pragma unroll
        for (int n = 0; n < 4; n++) wmma::fill_fragment(acc[m][n], 0.0f);

    const float* Ap = A + m0 * D_IN;
    float4 v[2];

    // ---- prologue: tile 0 ----
    ldgA(Ap, tid, v);
    cpB(sb + OFF_B0, g_W1bf, tid);
    asm volatile("cp.async.commit_group;" ::: "memory");
    stsA(smem, OFF_A0, tid, v);
    asm volatile("cp.async.wait_group 0;" ::: "memory");
    __syncthreads();

    // ---- mainloop: 16 K-tiles of 64 ----
#pragma unroll 1
    for (int t = 0; t < 16; t++) {
        const uint32_t acur = (t & 1) ? OFF_A1 : OFF_A0;
        const uint32_t bcur = (t & 1) ? OFF_B1 : OFF_B0;
        const uint32_t anxt = (t & 1) ? OFF_A0 : OFF_A1;
        const uint32_t bnxt = (t & 1) ? OFF_B0 : OFF_B1;

        if (t < 15) {
            ldgA(Ap + (t + 1) * BK, tid, v);
            cpB(sb + bnxt, g_W1bf + (long)(t + 1) * BK * H1_DIM, tid);
            asm volatile("cp.async.commit_group;" ::: "memory");
        }

        {
            const __nv_bfloat16* As = (const __nv_bfloat16*)(smem + acur);
            const __nv_bfloat16* Bs = (const __nv_bfloat16*)(smem + bcur);
#pragma unroll
            for (int ks = 0; ks < 4; ks++) {
                wmma::fragment<wmma::matrix_a, 16, 16, 16, __nv_bfloat16, wmma::row_major> a[2];
#pragma unroll
                for (int m = 0; m < 2; m++)
                    wmma::load_matrix_sync(a[m], As + (wm * 32 + m * 16) * A_LD + ks * 16, A_LD);
#pragma unroll
                for (int n = 0; n < 4; n++) {
                    wmma::fragment<wmma::matrix_b, 16, 16, 16, __nv_bfloat16, wmma::row_major> b;
                    wmma::load_matrix_sync(b, Bs + (ks * 16) * B_LD + wn * 64 + n * 16, B_LD);
#pragma unroll
                    for (int m = 0; m < 2; m++)
                        wmma::mma_sync(acc[m][n], a[m], b, acc[m][n]);
                }
            }
        }

        if (t < 15) {
            stsA(smem, anxt, tid, v);
            asm volatile("cp.async.wait_group 0;" ::: "memory");
        }
        __syncthreads();
    }

    // ---- epilogue: acc -> fp32 smem ----
    float* Hf = (float*)(smem + OFF_HF);
#pragma unroll
    for (int m = 0; m < 2; m++)
#pragma unroll
        for (int n = 0; n < 4; n++)
            wmma::store_matrix_sync(Hf + (wm * 32 + m * 16) * 516 + wn * 64 + n * 16,
                                    acc[m][n], 516, wmma::mem_row_major);
    __syncthreads();

    // ---- bias + relu + bf16 ----
    __nv_bfloat16* Hb = (__nv_bfloat16*)(smem + OFF_HB); // [64][520]
#pragma unroll
    for (int it = 0; it < 16; it++) {
        int f = tid + it * NTHREADS;   // 8192 float4 total
        int r = f >> 7;
        int q = f & 127;
        float4 x = *reinterpret_cast<const float4*>(Hf + r * 516 + q * 4);
        float x0 = fmaxf(x.x + b1s[q * 4 + 0], 0.0f);
        float x1 = fmaxf(x.y + b1s[q * 4 + 1], 0.0f);
        float x2 = fmaxf(x.z + b1s[q * 4 + 2], 0.0f);
        float x3 = fmaxf(x.w + b1s[q * 4 + 3], 0.0f);
        uint2 u;
        u.x = pack_bf16x2(x0, x1);
        u.y = pack_bf16x2(x2, x3);
        *reinterpret_cast<uint2*>(&Hb[r * 520 + q * 4]) = u;
    }
    __syncthreads();

    // ---- layer2: [64,512] @ [512,32] (8 warps active) ----
    float* outs = (float*)(smem + OFF_OUTS); // [64][36]
    if (wid < 8) {
        const int rg = wid >> 1;   // 0..3 -> rows rg*16
        const int cg = wid & 1;    // 0..1 -> cols cg*16
        wmma::fragment<wmma::accumulator, 16, 16, 16, float> acc2;
        wmma::fill_fragment(acc2, 0.0f);
        for (int kk = 0; kk < 32; kk++) {
            wmma::fragment<wmma::matrix_a, 16, 16, 16, __nv_bfloat16, wmma::row_major> a;
            wmma::fragment<wmma::matrix_b, 16, 16, 16, __nv_bfloat16, wmma::row_major> b;
            wmma::load_matrix_sync(a, &Hb[(rg * 16) * 520 + kk * 16], 520);
            wmma::load_matrix_sync(b, g_W2bf + (kk * 16) * H2_DIM + cg * 16, H2_DIM);
            wmma::mma_sync(acc2, a, b, acc2);
        }
        wmma::store_matrix_sync(&outs[(rg * 16) * 36 + cg * 16], acc2, 36, wmma::mem_row_major);
    }
    __syncthreads();

    // ---- layer3 + sigmoid ----
    if (tid < 64) {
        float logit = *b3;
#pragma unroll
        for (int n = 0; n < 32; n++)
            logit += (outs[tid * 36 + n] + b2s[n]) * W3s[n];
        g_logits[m0 + tid] = 1.0f / (1.0f + expf(-logit));
    }
}

// ============================================================
// topk: per-batch bitonic sort + masked top-k mean
// ============================================================
__global__ __launch_bounds__(1024, 1) void topk_kernel(const int* __restrict__ seq_len,
                                                       float* __restrict__ out) {
    __shared__ float vals[2048];
    __shared__ float red[32];
    const int b   = blockIdx.x;
    const int tid = threadIdx.x;
    const int s   = seq_len[b];

    for (int i = tid; i < 2048; i += 1024)
        vals[i] = (i < s) ? g_logits[(long)b * T_SEQ + i] : -INFINITY;
    __syncthreads();

    for (int k = 2; k <= 2048; k <<= 1) {
        for (int j = k >> 1; j > 0; j >>= 1) {
            for (int l = tid; l < 2048; l += 1024) {
                int ixj = l ^ j;
                if (ixj > l) {
                    float a = vals[l], c = vals[ixj];
                    bool up = ((l & k) == 0);
                    if (up ? (a < c) : (a > c)) { vals[l] = c; vals[ixj] = a; }
                }
            }
            __syncthreads();
        }
    }

    const int kb = s / 16 + 1;
    float sum = 0.0f;
    for (int i = tid; i < kb; i += 1024) sum += vals[i];
#pragma unroll
    for (int off = 16; off > 0; off >>= 1)
        sum += __shfl_down_sync(0xffffffffu, sum, off);
    if ((tid & 31) == 0) red[tid >> 5] = sum;
    __syncthreads();
    if (tid == 0) {
        float t = 0.0f;
#pragma unroll
        for (int w = 0; w < 32; w++) t += red[w];
        out[b] = t / (float)kb;
    }
}

// ============================================================
extern "C" void kernel_launch(void* const* d_in, const int* in_sizes, int n_in,
                              void* d_out, int out_size) {
    const float* avf = (const float*)d_in[0];
    const int*   seq = (const int*)  d_in[1];
    const float* W1  = (const float*)d_in[2];
    const float* b1  = (const float*)d_in[3];
    const float* W2  = (const float*)d_in[4];
    const float* b2  = (const float*)d_in[5];
    const float* W3  = (const float*)d_in[6];
    const float* b3  = (const float*)d_in[7];
    float* out = (float*)d_out;

    cudaFuncSetAttribute(fused_kernel, cudaFuncAttributeMaxDynamicSharedMemorySize, SMEM_TOTAL);

    prep_kernel<<<2048, 256>>>(W1, W2);
    fused_kernel<<<M_TOTAL / 64, NTHREADS, SMEM_TOTAL>>>(avf, b1, b2, W3, b3);
    topk_kernel<<<B_BATCH, 1024>>>(seq, out);
}

// round 7
// speedup vs baseline: 1.1927x; 1.1927x over previous
#include <cuda_runtime.h>
#include <cuda_bf16.h>
#include <mma.h>
#include <math.h>
#include <stdint.h>

using namespace nvcuda;

#define B_BATCH 64
#define T_SEQ   2048
#define D_IN    1024
#define H1_DIM  512
#define H2_DIM  32
#define M_TOTAL (B_BATCH * T_SEQ)   // 131072

#define BM    128
#define BN    256
#define BK    64
#define A_LD  80    // 160B row stride (mod 128 = 32) -> conflict-free LDSM
#define B_LD  272   // 544B row stride (mod 128 = 32) -> conflict-free LDSM
#define NT    256

// ---- gemm1 smem byte offsets ----
#define OFF_B0   0                    // 64 x 272 x 2 = 34816
#define OFF_B1   34816                // -> 69632
#define OFF_A0   69632                // 128 x 80 x 2 = 20480
#define OFF_A1   90112                // -> 110592 (mainloop end)
#define OFF_HF   0                    // epilogue alias: fp32 [128][260] = 133120
#define OFF_B1S  133120               // fp32[256] slice of b1
#define SMEM_G1  134144

// ---- device scratch ----
__device__ __nv_bfloat16 g_W1bf[D_IN * H1_DIM];    // [k][n] 1 MB
__device__ __nv_bfloat16 g_W2bf[H1_DIM * H2_DIM];  // 32 KB
__device__ __nv_bfloat16 g_h[(size_t)M_TOTAL * H1_DIM]; // 128 MB, post-ReLU bf16
__device__ float         g_logits[M_TOTAL];        // 512 KB

__device__ __forceinline__ uint32_t pack_bf16x2(float lo, float hi) {
    __nv_bfloat162 v = __floats2bfloat162_rn(lo, hi);
    return (uint32_t)__bfloat16_as_ushort(v.x) | ((uint32_t)__bfloat16_as_ushort(v.y) << 16);
}
__device__ __forceinline__ uint32_t smem_u32(const void* p) {
    uint32_t a;
    asm("{ .reg .u64 t; cvta.to.shared.u64 t, %1; cvt.u32.u64 %0, t; }" : "=r"(a) : "l"(p));
    return a;
}

// ============================================================
// Prep: convert W1, W2 to bf16
// ============================================================
__global__ void prep_kernel(const float* __restrict__ W1, const float* __restrict__ W2) {
    int i = blockIdx.x * blockDim.x + threadIdx.x;
    if (i < D_IN * H1_DIM)   g_W1bf[i] = __float2bfloat16(W1[i]);
    if (i < H1_DIM * H2_DIM) g_W2bf[i] = __float2bfloat16(W2[i]);
}

// ============================================================
// GEMM1: per CTA 128 rows x 256 cols; h = relu(A@W1 + b1) -> g_h (bf16)
// ============================================================
__device__ __forceinline__ void ldgA(const float* __restrict__ Ap, int tid, float4 v[8]) {
#pragma unroll
    for (int it = 0; it < 8; it++) {
        int f = tid + it * NT;         // 0..2047
        int r = f >> 4;                // row 0..127
        int q = f & 15;                // float4 idx (64 floats/row)
        v[it] = *reinterpret_cast<const float4*>(Ap + (long)r * D_IN + q * 4);
    }
}
__device__ __forceinline__ void stsA(char* smem, uint32_t aoff, int tid, const float4 v[8]) {
#pragma unroll
    for (int it = 0; it < 8; it++) {
        int f = tid + it * NT;
        int r = f >> 4;
        int q = f & 15;
        uint2 u;
        u.x = pack_bf16x2(v[it].x, v[it].y);
        u.y = pack_bf16x2(v[it].z, v[it].w);
        *reinterpret_cast<uint2*>(smem + aoff + r * (A_LD * 2) + q * 8) = u;
    }
}
__device__ __forceinline__ void cpB(uint32_t b_base, const __nv_bfloat16* __restrict__ Bsrc, int tid) {
    // 64 rows x 256 bf16 = 64 x 32 chunks of 16B
#pragma unroll
    for (int it = 0; it < 8; it++) {
        int c = tid + it * NT;         // 0..2047
        int row = c >> 5;              // 0..63
        int ch  = c & 31;              // 16B chunk
        uint32_t off = (uint32_t)(row * (B_LD * 2) + ch * 16);
        uint64_t g = __cvta_generic_to_global((const void*)(Bsrc + (long)row * H1_DIM + ch * 8));
        asm volatile("cp.async.cg.shared.global [%0], [%1], 16;" :: "r"(b_base + off), "l"(g));
    }
}

__global__ __launch_bounds__(NT, 1)
void gemm1_kernel(const float* __restrict__ A, const float* __restrict__ b1) {
    extern __shared__ char smem[];
    const uint32_t sb = smem_u32(smem);
    const int tid = threadIdx.x;
    const int wid = tid >> 5;
    const int bid = blockIdx.x;
    const long m0 = (long)(bid >> 1) * BM;
    const int  n0 = (bid & 1) * BN;

    float* b1s = (float*)(smem + OFF_B1S);
    b1s[tid] = b1[n0 + tid];           // 256 threads, 256 values

    // warp layout: 2 (M) x 4 (N); warp tile 64 x 64
    const int wm = wid >> 2;   // 0..1
    const int wn = wid & 3;    // 0..3

    wmma::fragment<wmma::accumulator, 16, 16, 16, float> acc[4][4];
#pragma unroll
    for (int m = 0; m < 4; m++)
#pragma unroll
        for (int n = 0; n < 4; n++) wmma::fill_fragment(acc[m][n], 0.0f);

    const float* Ap = A + m0 * D_IN;
    const __nv_bfloat16* Bp = g_W1bf + n0;
    float4 v[8];

    // ---- prologue: tile 0 ----
    ldgA(Ap, tid, v);
    cpB(sb + OFF_B0, Bp, tid);
    asm volatile("cp.async.commit_group;" ::: "memory");
    stsA(smem, OFF_A0, tid, v);
    asm volatile("cp.async.wait_group 0;" ::: "memory");
    __syncthreads();

    // ---- mainloop: 16 K-tiles of 64 ----
#pragma unroll 1
    for (int t = 0; t < 16; t++) {
        const uint32_t acur = (t & 1) ? OFF_A1 : OFF_A0;
        const uint32_t bcur = (t & 1) ? OFF_B1 : OFF_B0;
        const uint32_t anxt = (t & 1) ? OFF_A0 : OFF_A1;
        const uint32_t bnxt = (t & 1) ? OFF_B0 : OFF_B1;

        if (t < 15) {
            ldgA(Ap + (t + 1) * BK, tid, v);
            cpB(sb + bnxt, Bp + (long)(t + 1) * BK * H1_DIM, tid);
            asm volatile("cp.async.commit_group;" ::: "memory");
        }

        {
            const __nv_bfloat16* As = (const __nv_bfloat16*)(smem + acur);
            const __nv_bfloat16* Bs = (const __nv_bfloat16*)(smem + bcur);
#pragma unroll
            for (int ks = 0; ks < 4; ks++) {
                wmma::fragment<wmma::matrix_a, 16, 16, 16, __nv_bfloat16, wmma::row_major> a[4];
#pragma unroll
                for (int m = 0; m < 4; m++)
                    wmma::load_matrix_sync(a[m], As + (wm * 64 + m * 16) * A_LD + ks * 16, A_LD);
#pragma unroll
                for (int n = 0; n < 4; n++) {
                    wmma::fragment<wmma::matrix_b, 16, 16, 16, __nv_bfloat16, wmma::row_major> b;
                    wmma::load_matrix_sync(b, Bs + (ks * 16) * B_LD + wn * 64 + n * 16, B_LD);
#pragma unroll
                    for (int m = 0; m < 4; m++)
                        wmma::mma_sync(acc[m][n], a[m], b, acc[m][n]);
                }
            }
        }

        if (t < 15) {
            stsA(smem, anxt, tid, v);
            asm volatile("cp.async.wait_group 0;" ::: "memory");
        }
        __syncthreads();
    }

    // ---- epilogue: acc -> fp32 smem -> bias+relu -> bf16 global ----
    float* Hf = (float*)(smem + OFF_HF);   // [128][260]
#pragma unroll
    for (int m = 0; m < 4; m++)
#pragma unroll
        for (int n = 0; n < 4; n++)
            wmma::store_matrix_sync(Hf + (wm * 64 + m * 16) * 260 + wn * 64 + n * 16,
                                    acc[m][n], 260, wmma::mem_row_major);
    __syncthreads();

    // 128 rows x 256 cols = 8192 float4
    __nv_bfloat16* hout = g_h + m0 * H1_DIM + n0;
#pragma unroll
    for (int it = 0; it < 32; it++) {
        int f = tid + it * NT;
        int r = f >> 6;                // row 0..127 (64 float4 per row)
        int q = f & 63;
        float4 x = *reinterpret_cast<const float4*>(Hf + r * 260 + q * 4);
        float x0 = fmaxf(x.x + b1s[q * 4 + 0], 0.0f);
        float x1 = fmaxf(x.y + b1s[q * 4 + 1], 0.0f);
        float x2 = fmaxf(x.z + b1s[q * 4 + 2], 0.0f);
        float x3 = fmaxf(x.w + b1s[q * 4 + 3], 0.0f);
        uint2 u;
        u.x = pack_bf16x2(x0, x1);
        u.y = pack_bf16x2(x2, x3);
        *reinterpret_cast<uint2*>(hout + (long)r * H1_DIM + q * 4) = u;
    }
}

// ============================================================
// mlp2: 64 rows/CTA: out = h @ W2 + b2; logit = out.W3 + b3; sigmoid
// ============================================================
#define H_LD 528   // 1056B stride (mod 128 = 32)
#define M2_HS   0                     // bf16 [64][528] = 67584
#define M2_OUTS 67584                 // fp32 [64][36] = 9216
#define M2_B2S  76800                 // fp32[32]
#define M2_W3S  76928                 // fp32[32]
#define SMEM_M2 77056

__global__ __launch_bounds__(256, 1)
void mlp2_kernel(const float* __restrict__ b2, const float* __restrict__ W3,
                 const float* __restrict__ b3) {
    extern __shared__ char smem[];
    const uint32_t sb = smem_u32(smem);
    const int tid = threadIdx.x;
    const int wid = tid >> 5;
    const long m0 = (long)blockIdx.x * 64;

    float* b2s = (float*)(smem + M2_B2S);
    float* W3s = (float*)(smem + M2_W3S);
    if (tid < 32)        b2s[tid] = b2[tid];
    else if (tid < 64)   W3s[tid - 32] = W3[tid - 32];

    // load h tile 64x512 bf16 via cp.async: 64 rows x 64 chunks of 16B
    const __nv_bfloat16* hp = g_h + m0 * H1_DIM;
#pragma unroll
    for (int it = 0; it < 16; it++) {
        int c = tid + it * 256;
        int row = c >> 6;
        int ch  = c & 63;
        uint32_t off = (uint32_t)(M2_HS + row * (H_LD * 2) + ch * 16);
        uint64_t g = __cvta_generic_to_global((const void*)(hp + (long)row * H1_DIM + ch * 8));
        asm volatile("cp.async.cg.shared.global [%0], [%1], 16;" :: "r"(sb + off), "l"(g));
    }
    asm volatile("cp.async.commit_group;" ::: "memory");
    asm volatile("cp.async.wait_group 0;" ::: "memory");
    __syncthreads();

    const __nv_bfloat16* Hs = (const __nv_bfloat16*)(smem + M2_HS);
    float* outs = (float*)(smem + M2_OUTS);   // [64][36]
    {
        const int rg = wid >> 1;   // 0..3 -> rows rg*16
        const int cg = wid & 1;    // 0..1 -> cols cg*16
        wmma::fragment<wmma::accumulator, 16, 16, 16, float> acc2;
        wmma::fill_fragment(acc2, 0.0f);
#pragma unroll 4
        for (int kk = 0; kk < 32; kk++) {
            wmma::fragment<wmma::matrix_a, 16, 16, 16, __nv_bfloat16, wmma::row_major> a;
            wmma::fragment<wmma::matrix_b, 16, 16, 16, __nv_bfloat16, wmma::row_major> b;
            wmma::load_matrix_sync(a, Hs + (rg * 16) * H_LD + kk * 16, H_LD);
            wmma::load_matrix_sync(b, g_W2bf + (kk * 16) * H2_DIM + cg * 16, H2_DIM);
            wmma::mma_sync(acc2, a, b, acc2);
        }
        wmma::store_matrix_sync(&outs[(rg * 16) * 36 + cg * 16], acc2, 36, wmma::mem_row_major);
    }
    __syncthreads();

    if (tid < 64) {
        float logit = *b3;
#pragma unroll
        for (int n = 0; n < 32; n++)
            logit += (outs[tid * 36 + n] + b2s[n]) * W3s[n];
        g_logits[m0 + tid] = 1.0f / (1.0f + expf(-logit));
    }
}

// ============================================================
// topk: per-batch bitonic sort + masked top-k mean
// ============================================================
__global__ __launch_bounds__(1024, 1) void topk_kernel(const int* __restrict__ seq_len,
                                                       float* __restrict__ out) {
    __shared__ float vals[2048];
    __shared__ float red[32];
    const int b   = blockIdx.x;
    const int tid = threadIdx.x;
    const int s   = seq_len[b];

    for (int i = tid; i < 2048; i += 1024)
        vals[i] = (i < s) ? g_logits[(long)b * T_SEQ + i] : -INFINITY;
    __syncthreads();

    for (int k = 2; k <= 2048; k <<= 1) {
        for (int j = k >> 1; j > 0; j >>= 1) {
            for (int l = tid; l < 2048; l += 1024) {
                int ixj = l ^ j;
                if (ixj > l) {
                    float a = vals[l], c = vals[ixj];
                    bool up = ((l & k) == 0);
                    if (up ? (a < c) : (a > c)) { vals[l] = c; vals[ixj] = a; }
                }
            }
            __syncthreads();
        }
    }

    const int kb = s / 16 + 1;
    float sum = 0.0f;
    for (int i = tid; i < kb; i += 1024) sum += vals[i];
#pragma unroll
    for (int off = 16; off > 0; off >>= 1)
        sum += __shfl_down_sync(0xffffffffu, sum, off);
    if ((tid & 31) == 0) red[tid >> 5] = sum;
    __syncthreads();
    if (tid == 0) {
        float t = 0.0f;
#pragma unroll
        for (int w = 0; w < 32; w++) t += red[w];
        out[b] = t / (float)kb;
    }
}

// ============================================================
extern "C" void kernel_launch(void* const* d_in, const int* in_sizes, int n_in,
                              void* d_out, int out_size) {
    const float* avf = (const float*)d_in[0];
    const int*   seq = (const int*)  d_in[1];
    const float* W1  = (const float*)d_in[2];
    const float* b1  = (const float*)d_in[3];
    const float* W2  = (const float*)d_in[4];
    const float* b2  = (const float*)d_in[5];
    const float* W3  = (const float*)d_in[6];
    const float* b3  = (const float*)d_in[7];
    float* out = (float*)d_out;

    cudaFuncSetAttribute(gemm1_kernel, cudaFuncAttributeMaxDynamicSharedMemorySize, SMEM_G1);
    cudaFuncSetAttribute(mlp2_kernel,  cudaFuncAttributeMaxDynamicSharedMemorySize, SMEM_M2);

    prep_kernel<<<2048, 256>>>(W1, W2);
    gemm1_kernel<<<(M_TOTAL / BM) * 2, NT, SMEM_G1>>>(avf, b1);
    mlp2_kernel<<<M_TOTAL / 64, 256, SMEM_M2>>>(b2, W3, b3);
    topk_kernel<<<B_BATCH, 1024>>>(seq, out);
}